// round 13
// baseline (speedup 1.0000x reference)
#include <cuda_runtime.h>
#include <math.h>

#define NN 50000
#define EE 800000
#define CH 128
#define LATD 64
#define NG 256
#define MAXN 320

// output layout (floats): adj | mu | logvar | mask
#define ADJ_OFF 0
#define MU_OFF   (NG*MAXN*MAXN)
#define LV_OFF   (MU_OFF + NN*LATD)
#define MASK_OFF (LV_OFF + NN*LATD)

#define NBLK 196                        // ceil(NN/256)

// ---- scratch (device globals; never passed as kernel args from host) ----
__device__ float g_dinv[NN];
__device__ float g_xh [NN*CH];
__device__ float g_h  [NN*CH];
__device__ float g_z  [NG*MAXN*LATD];
__device__ float g_Wh [CH*CH];
__device__ __align__(16) float g_bh [CH];
__device__ int   g_cnt[NG];
__device__ int   g_ptr[NG];
__device__ int   g_ideg[NN];
__device__ int   g_off [NN + 1];
__device__ int   g_cur [NN];
__device__ int   g_bsum[NBLK];
__device__ int   g_boff[NBLK];
__device__ int   g_es  [EE];
__device__ float g_ew  [EE];

typedef unsigned long long ull;

__device__ __forceinline__ ull dup2(float a) {
    ull r; asm("mov.b64 %0, {%1, %1};" : "=l"(r) : "f"(a)); return r;
}
__device__ __forceinline__ void ffma2(ull& d, ull a, ull b) {
    asm("fma.rn.f32x2 %0, %1, %2, %3;" : "=l"(d) : "l"(a), "l"(b), "l"(d));
}
__device__ __forceinline__ void fadd2(ull& d, ull a, ull b) {
    asm("add.rn.f32x2 %0, %1, %2;" : "=l"(d) : "l"(a), "l"(b));
}

// FMA-only e^t (t bounded |t| <= ~30): 2^(t*log2e) via floor + deg-5 poly
__device__ __forceinline__ float fast_exp(float t) {
    float u = fminf(fmaxf(t * 1.4426950408889634f, -30.0f), 30.0f);
    float fl = floorf(u);
    float fr = u - fl;
    float p = 1.33336498e-3f;
    p = fmaf(p, fr, 9.61011722e-3f);
    p = fmaf(p, fr, 5.55036540e-2f);
    p = fmaf(p, fr, 2.40226506e-1f);
    p = fmaf(p, fr, 6.93147182e-1f);
    p = fmaf(p, fr, 1.0f);
    float s = __int_as_float(((int)fl + 127) << 23);
    return p * s;
}

__device__ __forceinline__ float fast_sigmoid(float t) {
    float ex = fast_exp(t);
    float d = 1.0f + ex;
    float r = __int_as_float(0x7EF127EA - __float_as_int(d));
    r = r * (2.0f - d * r);
    r = r * (2.0f - d * r);
    return ex * r;                       // sigmoid(t) = e^t / (1+e^t)
}

// ---------------------------------------------------------------- zero / init (+ head packing fused)
__global__ void k_zero(float* __restrict__ out,
                       const float* __restrict__ Wmu, const float* __restrict__ bmu,
                       const float* __restrict__ Wlv, const float* __restrict__ blv) {
    int i = blockIdx.x * blockDim.x + threadIdx.x;
    if (i < NG*MAXN*LATD) g_z[i] = 0.0f;
    if (i < NN)           g_ideg[i] = 0;
    if (i < NG)           g_cnt[i] = 0;
    if (i < NG*MAXN)      out[MASK_OFF + i] = 0.0f;
    if (i < CH * CH) {
        int k = i >> 7, j = i & 127;
        g_Wh[i] = (j < LATD) ? Wmu[k * LATD + j] : Wlv[k * LATD + (j - LATD)];
    }
    if (i < CH) g_bh[i] = (i < LATD) ? bmu[i] : blv[i - LATD];
}

__global__ void k_hist(const int* __restrict__ dst) {
    int e = blockIdx.x * blockDim.x + threadIdx.x;
    if (e < EE) atomicAdd(&g_ideg[dst[e]], 1);
}

__global__ void k_rsqrt(const int* __restrict__ batch) {
    int i = blockIdx.x * blockDim.x + threadIdx.x;
    if (i < NN) {
        g_dinv[i] = rsqrtf((float)(g_ideg[i] + 1));
        atomicAdd(&g_cnt[batch[i]], 1);
    }
}

// ---- 3-phase parallel scan of g_ideg -> g_off/g_cur ----
__global__ void k_scan1() {
    int idx = blockIdx.x * 256 + threadIdx.x;
    int v = (idx < NN) ? g_ideg[idx] : 0;
    int lane = threadIdx.x & 31, wid = threadIdx.x >> 5;
    int s = v;
#pragma unroll
    for (int o = 1; o < 32; o <<= 1) {
        int t = __shfl_up_sync(~0u, s, o);
        if (lane >= o) s += t;
    }
    __shared__ int ws[8];
    if (lane == 31) ws[wid] = s;
    __syncthreads();
    if (threadIdx.x < 8) {
        int t = ws[threadIdx.x], u = t;
#pragma unroll
        for (int o = 1; o < 8; o <<= 1) {
            int p = __shfl_up_sync(0xff, u, o);
            if (threadIdx.x >= o) u += p;
        }
        ws[threadIdx.x] = u - t;
    }
    __syncthreads();
    int exc = s - v + ws[wid];
    if (idx < NN) g_off[idx] = exc;
    if (threadIdx.x == 255) g_bsum[blockIdx.x] = exc + v;
}

// scan of block sums + (fused) graph-pointer scan
__global__ void k_scan2() {
    int t = threadIdx.x;
    {
        int v = (t < NBLK) ? g_bsum[t] : 0;
        int lane = t & 31, wid = t >> 5;
        int s = v;
#pragma unroll
        for (int o = 1; o < 32; o <<= 1) {
            int p = __shfl_up_sync(~0u, s, o);
            if (lane >= o) s += p;
        }
        __shared__ int ws[8];
        if (lane == 31) ws[wid] = s;
        __syncthreads();
        if (t < 8) {
            int a = ws[t], u = a;
#pragma unroll
            for (int o = 1; o < 8; o <<= 1) {
                int p = __shfl_up_sync(0xff, u, o);
                if (t >= o) u += p;
            }
            ws[t] = u - a;
        }
        __syncthreads();
        if (t < NBLK) g_boff[t] = s - v + ws[wid];
    }
    __syncthreads();
    // graph ptr scan (NG = 256)
    {
        __shared__ int sp[NG];
        int my = g_cnt[t];
        sp[t] = my;
        __syncthreads();
        for (int off = 1; off < NG; off <<= 1) {
            int v = (t >= off) ? sp[t - off] : 0;
            __syncthreads();
            sp[t] += v;
            __syncthreads();
        }
        g_ptr[t] = sp[t] - my;
    }
}

__global__ void k_scan3() {
    int idx = blockIdx.x * 256 + threadIdx.x;
    if (idx < NN) {
        int o = g_off[idx] + g_boff[blockIdx.x];
        g_off[idx] = o;
        g_cur[idx] = o;
    }
    if (idx == 0) g_off[NN] = EE;
}

__global__ void k_scatter(const int* __restrict__ src, const int* __restrict__ dst) {
    int e = blockIdx.x * blockDim.x + threadIdx.x;
    if (e >= EE) return;
    int s = src[e], d = dst[e];
    int pos = atomicAdd(&g_cur[d], 1);
    g_es[pos] = s;
    g_ew[pos] = g_dinv[s] * g_dinv[d];
}

// ---------------------------------------------------------------- GEMM  C = A @ W
// mode 0: A=x ext, W=W1 -> g_xh;  mode 1: A=g_h, W=W2 -> g_xh
// mode 2: A=g_h, W=g_Wh (+g_bh); fused epilogue -> mu/lv/z/mask
// tile 128x128, 256 threads; thread owns rows ty+16i (i<8), col pairs 2tx+32j (j<4).
// Per k: 8x LDS.32 A (warp-broadcast, 1 wf) + 4x LDS.64 B (2 wf) = 16 wf / 32 FFMA2.
__global__ __launch_bounds__(256, 2)
void k_gemm(const float* __restrict__ Aext, const float* __restrict__ Wext,
            const int* __restrict__ batch, const float* __restrict__ eps,
            float* __restrict__ out, int mode) {
    __shared__ __align__(16) float As[128][33];
    __shared__ __align__(16) float Ws[32][128];
    const float* A = (mode == 0) ? Aext : g_h;
    const float* W = (mode == 2) ? g_Wh : Wext;

    int tx = threadIdx.x & 15;
    int ty = threadIdx.x >> 4;
    int tid = threadIdx.x;
    int row0 = blockIdx.x * 128;

    ull acc[8][4];
#pragma unroll
    for (int i = 0; i < 8; i++)
#pragma unroll
        for (int j = 0; j < 4; j++) acc[i][j] = 0ull;

    for (int kc = 0; kc < CH; kc += 32) {
        // A chunk 128x32, 16 scalar loads per thread
#pragma unroll
        for (int i = tid; i < 128 * 32; i += 256) {
            int r = i >> 5, kk = i & 31;
            int gr = row0 + r;
            As[r][kk] = (gr < NN) ? A[(size_t)gr * CH + kc + kk] : 0.0f;
        }
        // W chunk 32x128
#pragma unroll
        for (int i = tid; i < 32 * 128; i += 256) {
            int r = i >> 7, c = i & 127;
            Ws[r][c] = W[(kc + r) * CH + c];
        }
        __syncthreads();
#pragma unroll
        for (int kk = 0; kk < 32; kk++) {
            ull aa[8], w2[4];
#pragma unroll
            for (int i = 0; i < 8; i++) aa[i] = dup2(As[ty + 16 * i][kk]);
#pragma unroll
            for (int j = 0; j < 4; j++)
                w2[j] = *(const ull*)&Ws[kk][2 * tx + 32 * j];
#pragma unroll
            for (int i = 0; i < 8; i++)
#pragma unroll
                for (int j = 0; j < 4; j++) ffma2(acc[i][j], aa[i], w2[j]);
        }
        __syncthreads();
    }

    if (mode != 2) {
#pragma unroll
        for (int i = 0; i < 8; i++) {
            int gr = row0 + ty + 16 * i;
            if (gr < NN) {
#pragma unroll
                for (int j = 0; j < 4; j++) {
                    int c = 2 * tx + 32 * j;
                    *(ull*)&g_xh[(size_t)gr * CH + c] = acc[i][j];
                }
            }
        }
    } else {
        // fused heads epilogue: cols 0..63 = mu, 64..127 = lv; j and j+2 share latent index
#pragma unroll
        for (int i = 0; i < 8; i++) {
            int gr = row0 + ty + 16 * i;
            if (gr >= NN) continue;
            int b = batch[gr];
            int pos = gr - g_ptr[b];
#pragma unroll
            for (int jp = 0; jp < 2; jp++) {
                int c = 2 * tx + 32 * jp;                  // latent index (even)
                ull mu2 = acc[i][jp];
                ull lv2 = acc[i][jp + 2];
                fadd2(mu2, mu2, *(const ull*)&g_bh[c]);
                fadd2(lv2, lv2, *(const ull*)&g_bh[c + 64]);
                *(ull*)&out[MU_OFF + (size_t)gr * LATD + c] = mu2;
                *(ull*)&out[LV_OFF + (size_t)gr * LATD + c] = lv2;
                float2 m = *(float2*)&mu2;
                float2 l = *(float2*)&lv2;
                ull e2 = *(const ull*)&eps[(size_t)gr * LATD + c];
                float2 ef = *(float2*)&e2;
                float2 zz;
                zz.x = fmaf(ef.x, fast_exp(0.5f * fminf(fmaxf(l.x, -20.0f), 20.0f)), m.x);
                zz.y = fmaf(ef.y, fast_exp(0.5f * fminf(fmaxf(l.y, -20.0f), 20.0f)), m.y);
                if (pos < MAXN) {
                    *(ull*)&g_z[((size_t)b * MAXN + pos) * LATD + c] = *(ull*)&zz;
                    if (c == 0) out[MASK_OFF + b * MAXN + pos] = 1.0f;
                }
            }
        }
    }
}

// ---------------------------------------------------------------- CSR aggregation: warp per node (fp32 gathers)
__global__ __launch_bounds__(256)
void k_agg(const float* __restrict__ bias) {
    int node = (blockIdx.x * blockDim.x + threadIdx.x) >> 5;
    if (node >= NN) return;
    int lane = threadIdx.x & 31;

    float dv = g_dinv[node];
    ull sn = dup2(dv * dv);
    float4 self = ((const float4*)(g_xh + (size_t)node * CH))[lane];
    ull acc0 = 0ull, acc1 = 0ull;
    ffma2(acc0, sn, *(ull*)&self.x);
    ffma2(acc1, sn, *(ull*)&self.z);

    int e = g_off[node];
    int end = g_off[node + 1];

    for (; e + 4 <= end; e += 4) {
        int s0 = g_es[e], s1 = g_es[e+1], s2 = g_es[e+2], s3 = g_es[e+3];
        ull w0 = dup2(g_ew[e]),   w1 = dup2(g_ew[e+1]);
        ull w2 = dup2(g_ew[e+2]), w3 = dup2(g_ew[e+3]);
        float4 v0 = ((const float4*)(g_xh + (size_t)s0 * CH))[lane];
        float4 v1 = ((const float4*)(g_xh + (size_t)s1 * CH))[lane];
        float4 v2 = ((const float4*)(g_xh + (size_t)s2 * CH))[lane];
        float4 v3 = ((const float4*)(g_xh + (size_t)s3 * CH))[lane];
        ffma2(acc0, w0, *(ull*)&v0.x); ffma2(acc1, w0, *(ull*)&v0.z);
        ffma2(acc0, w1, *(ull*)&v1.x); ffma2(acc1, w1, *(ull*)&v1.z);
        ffma2(acc0, w2, *(ull*)&v2.x); ffma2(acc1, w2, *(ull*)&v2.z);
        ffma2(acc0, w3, *(ull*)&v3.x); ffma2(acc1, w3, *(ull*)&v3.z);
    }
    for (; e < end; e++) {
        int s = g_es[e];
        ull w = dup2(g_ew[e]);
        float4 v = ((const float4*)(g_xh + (size_t)s * CH))[lane];
        ffma2(acc0, w, *(ull*)&v.x);
        ffma2(acc1, w, *(ull*)&v.z);
    }

    float4 b = ((const float4*)bias)[lane];
    float2 a0 = *(float2*)&acc0;
    float2 a1 = *(float2*)&acc1;
    float4 r;
    r.x = fmaxf(a0.x + b.x, 0.0f);
    r.y = fmaxf(a0.y + b.y, 0.0f);
    r.z = fmaxf(a1.x + b.z, 0.0f);
    r.w = fmaxf(a1.y + b.w, 0.0f);
    ((float4*)(g_h + (size_t)node * CH))[lane] = r;
}

// ---------------------------------------------------------------- decoder: per-graph z @ z^T -> sigmoid
// tile 160x160, 512 threads; thread owns rows ty+32i (i<5), col pairs 2tx+32j (j<5)
__global__ __launch_bounds__(512, 1)
void k_adj(const float* __restrict__ dec_bias, float* __restrict__ out) {
    __shared__ __align__(16) float As [160][65];
    __shared__ __align__(16) float BsT[64][162];
    int b = blockIdx.z;
    int r0 = blockIdx.y * 160;
    int c0 = blockIdx.x * 160;
    int tx = threadIdx.x & 15;
    int ty = threadIdx.x >> 4;          // 0..31
    int tid = threadIdx.x;
    const float* zb = g_z + (size_t)b * MAXN * LATD;

#pragma unroll
    for (int i = tid; i < 160 * 16; i += 512) {
        int r = i >> 4, k4 = (i & 15) * 4;
        float4 va = *(const float4*)&zb[(size_t)(r0 + r) * LATD + k4];
        As[r][k4] = va.x; As[r][k4+1] = va.y; As[r][k4+2] = va.z; As[r][k4+3] = va.w;
        float4 vb = *(const float4*)&zb[(size_t)(c0 + r) * LATD + k4];
        BsT[k4  ][r] = vb.x;
        BsT[k4+1][r] = vb.y;
        BsT[k4+2][r] = vb.z;
        BsT[k4+3][r] = vb.w;
    }
    __syncthreads();

    ull acc[5][5];
#pragma unroll
    for (int i = 0; i < 5; i++)
#pragma unroll
        for (int j = 0; j < 5; j++) acc[i][j] = 0ull;

#pragma unroll 4
    for (int k = 0; k < 64; k++) {
        ull aa[5], c2[5];
#pragma unroll
        for (int i = 0; i < 5; i++) aa[i] = dup2(As[ty + 32 * i][k]);
#pragma unroll
        for (int j = 0; j < 5; j++)
            c2[j] = *(const ull*)&BsT[k][2 * tx + 32 * j];
#pragma unroll
        for (int i = 0; i < 5; i++)
#pragma unroll
            for (int j = 0; j < 5; j++) ffma2(acc[i][j], aa[i], c2[j]);
    }

    float bias = dec_bias[0];
    const float SC = 0.125f;
#pragma unroll
    for (int i = 0; i < 5; i++) {
        int row = r0 + ty + 32 * i;
        size_t base = ((size_t)b * MAXN + row) * MAXN + c0;
#pragma unroll
        for (int j = 0; j < 5; j++) {
            int cp = 2 * tx + 32 * j;
            float2 a = *(float2*)&acc[i][j];
            float2 o;
            o.x = fast_sigmoid(fmaf(SC, a.x, bias));
            o.y = fast_sigmoid(fmaf(SC, a.y, bias));
            *(float2*)&out[base + cp] = o;
        }
    }
}

// ================================================================ launch
extern "C" void kernel_launch(void* const* d_in, const int* in_sizes, int n_in,
                              void* d_out, int out_size) {
    const float* x    = (const float*)d_in[0];
    const int*   ei   = (const int*)  d_in[1];
    const int*   batch= (const int*)  d_in[2];
    const float* eps  = (const float*)d_in[3];
    const float* W1   = (const float*)d_in[4];
    const float* b1   = (const float*)d_in[5];
    const float* W2   = (const float*)d_in[6];
    const float* b2   = (const float*)d_in[7];
    const float* Wmu  = (const float*)d_in[8];
    const float* bmu  = (const float*)d_in[9];
    const float* Wlv  = (const float*)d_in[10];
    const float* blv  = (const float*)d_in[11];
    const float* dbias= (const float*)d_in[12];
    float* out = (float*)d_out;

    const int* src = ei;
    const int* dst = ei + EE;

    int gemm_blocks = (NN + 127) / 128;
    int agg_blocks  = (NN * 32 + 255) / 256;

    // our 4th launch is what ncu captures: keep the mode-0 GEMM there.
    k_zero<<<(NG*MAXN*LATD + 255) / 256, 256>>>(out, Wmu, bmu, Wlv, blv);   // 1
    k_hist<<<(EE + 255) / 256, 256>>>(dst);                                  // 2
    k_rsqrt<<<(NN + 255) / 256, 256>>>(batch);                               // 3
    k_gemm<<<gemm_blocks, 256>>>(x, W1, nullptr, nullptr, out, 0);           // 4 <- profiled
    k_scan1<<<NBLK, 256>>>();                                                // 5
    k_scan2<<<1, 256>>>();                                                   // 6
    k_scan3<<<NBLK, 256>>>();                                                // 7
    k_scatter<<<(EE + 255) / 256, 256>>>(src, dst);                          // 8
    k_agg<<<agg_blocks, 256>>>(b1);                                          // 9
    k_gemm<<<gemm_blocks, 256>>>(nullptr, W2, nullptr, nullptr, out, 1);     // 10
    k_agg<<<agg_blocks, 256>>>(b2);                                          // 11
    k_gemm<<<gemm_blocks, 256>>>(nullptr, nullptr, batch, eps, out, 2);      // 12 (z fused)
    dim3 agrid(2, 2, NG);
    k_adj<<<agrid, 512>>>(dbias, out);                                       // 13
}

// round 16
// speedup vs baseline: 1.4700x; 1.4700x over previous
#include <cuda_runtime.h>
#include <math.h>

#define NN 50000
#define EE 800000
#define CH 128
#define LATD 64
#define NG 256
#define MAXN 320

// output layout (floats): adj | mu | logvar | mask
#define ADJ_OFF 0
#define MU_OFF   (NG*MAXN*MAXN)
#define LV_OFF   (MU_OFF + NN*LATD)
#define MASK_OFF (LV_OFF + NN*LATD)

#define NBLK 196                        // ceil(NN/256)

// ---- scratch (device globals; never passed as kernel args from host) ----
__device__ float g_dinv[NN];
__device__ float g_xh [NN*CH];
__device__ float g_h  [NN*CH];
__device__ float g_z  [NG*MAXN*LATD];
__device__ float g_Wh [CH*CH];
__device__ __align__(16) float g_bh [CH];
__device__ int   g_cnt[NG];
__device__ int   g_ptr[NG];
__device__ int   g_ideg[NN];
__device__ int   g_off [NN + 1];
__device__ int   g_cur [NN];
__device__ int   g_bsum[NBLK];
__device__ int   g_boff[NBLK];
__device__ int   g_es  [EE];
__device__ float g_ew  [EE];

typedef unsigned long long ull;

__device__ __forceinline__ ull dup2(float a) {
    ull r; asm("mov.b64 %0, {%1, %1};" : "=l"(r) : "f"(a)); return r;
}
__device__ __forceinline__ void ffma2(ull& d, ull a, ull b) {
    asm("fma.rn.f32x2 %0, %1, %2, %3;" : "=l"(d) : "l"(a), "l"(b), "l"(d));
}
__device__ __forceinline__ void fadd2(ull& d, ull a, ull b) {
    asm("add.rn.f32x2 %0, %1, %2;" : "=l"(d) : "l"(a), "l"(b));
}

// FMA-only e^t (t bounded |t| <= ~30): 2^(t*log2e) via floor + deg-5 poly
__device__ __forceinline__ float fast_exp(float t) {
    float u = fminf(fmaxf(t * 1.4426950408889634f, -30.0f), 30.0f);
    float fl = floorf(u);
    float fr = u - fl;
    float p = 1.33336498e-3f;
    p = fmaf(p, fr, 9.61011722e-3f);
    p = fmaf(p, fr, 5.55036540e-2f);
    p = fmaf(p, fr, 2.40226506e-1f);
    p = fmaf(p, fr, 6.93147182e-1f);
    p = fmaf(p, fr, 1.0f);
    float s = __int_as_float(((int)fl + 127) << 23);
    return p * s;
}

__device__ __forceinline__ float fast_sigmoid(float t) {
    float ex = fast_exp(t);
    float d = 1.0f + ex;
    float r = __int_as_float(0x7EF127EA - __float_as_int(d));
    r = r * (2.0f - d * r);
    r = r * (2.0f - d * r);
    return ex * r;                       // sigmoid(t) = e^t / (1+e^t)
}

// ---------------------------------------------------------------- zero / init (+ head packing fused)
__global__ void k_zero(float* __restrict__ out,
                       const float* __restrict__ Wmu, const float* __restrict__ bmu,
                       const float* __restrict__ Wlv, const float* __restrict__ blv) {
    int i = blockIdx.x * blockDim.x + threadIdx.x;
    if (i < NG*MAXN*LATD) g_z[i] = 0.0f;
    if (i < NN)           g_ideg[i] = 0;
    if (i < NG)           g_cnt[i] = 0;
    if (i < NG*MAXN)      out[MASK_OFF + i] = 0.0f;
    if (i < CH * CH) {
        int k = i >> 7, j = i & 127;
        g_Wh[i] = (j < LATD) ? Wmu[k * LATD + j] : Wlv[k * LATD + (j - LATD)];
    }
    if (i < CH) g_bh[i] = (i < LATD) ? bmu[i] : blv[i - LATD];
}

__global__ void k_hist(const int* __restrict__ dst) {
    int e = blockIdx.x * blockDim.x + threadIdx.x;
    if (e < EE) atomicAdd(&g_ideg[dst[e]], 1);
}

__global__ void k_rsqrt(const int* __restrict__ batch) {
    int i = blockIdx.x * blockDim.x + threadIdx.x;
    if (i < NN) {
        g_dinv[i] = rsqrtf((float)(g_ideg[i] + 1));
        atomicAdd(&g_cnt[batch[i]], 1);
    }
}

// ---- 3-phase parallel scan of g_ideg -> g_off/g_cur ----
__global__ void k_scan1() {
    int idx = blockIdx.x * 256 + threadIdx.x;
    int v = (idx < NN) ? g_ideg[idx] : 0;
    int lane = threadIdx.x & 31, wid = threadIdx.x >> 5;
    int s = v;
#pragma unroll
    for (int o = 1; o < 32; o <<= 1) {
        int t = __shfl_up_sync(~0u, s, o);
        if (lane >= o) s += t;
    }
    __shared__ int ws[8];
    if (lane == 31) ws[wid] = s;
    __syncthreads();
    if (threadIdx.x < 8) {
        int t = ws[threadIdx.x], u = t;
#pragma unroll
        for (int o = 1; o < 8; o <<= 1) {
            int p = __shfl_up_sync(0xff, u, o);
            if (threadIdx.x >= o) u += p;
        }
        ws[threadIdx.x] = u - t;
    }
    __syncthreads();
    int exc = s - v + ws[wid];
    if (idx < NN) g_off[idx] = exc;
    if (threadIdx.x == 255) g_bsum[blockIdx.x] = exc + v;
}

// scan of block sums + (fused) graph-pointer scan
__global__ void k_scan2() {
    int t = threadIdx.x;
    {
        int v = (t < NBLK) ? g_bsum[t] : 0;
        int lane = t & 31, wid = t >> 5;
        int s = v;
#pragma unroll
        for (int o = 1; o < 32; o <<= 1) {
            int p = __shfl_up_sync(~0u, s, o);
            if (lane >= o) s += p;
        }
        __shared__ int ws[8];
        if (lane == 31) ws[wid] = s;
        __syncthreads();
        if (t < 8) {
            int a = ws[t], u = a;
#pragma unroll
            for (int o = 1; o < 8; o <<= 1) {
                int p = __shfl_up_sync(0xff, u, o);
                if (t >= o) u += p;
            }
            ws[t] = u - a;
        }
        __syncthreads();
        if (t < NBLK) g_boff[t] = s - v + ws[wid];
    }
    __syncthreads();
    // graph ptr scan (NG = 256)
    {
        __shared__ int sp[NG];
        int my = g_cnt[t];
        sp[t] = my;
        __syncthreads();
        for (int off = 1; off < NG; off <<= 1) {
            int v = (t >= off) ? sp[t - off] : 0;
            __syncthreads();
            sp[t] += v;
            __syncthreads();
        }
        g_ptr[t] = sp[t] - my;
    }
}

__global__ void k_scan3() {
    int idx = blockIdx.x * 256 + threadIdx.x;
    if (idx < NN) {
        int o = g_off[idx] + g_boff[blockIdx.x];
        g_off[idx] = o;
        g_cur[idx] = o;
    }
    if (idx == 0) g_off[NN] = EE;
}

__global__ void k_scatter(const int* __restrict__ src, const int* __restrict__ dst) {
    int e = blockIdx.x * blockDim.x + threadIdx.x;
    if (e >= EE) return;
    int s = src[e], d = dst[e];
    int pos = atomicAdd(&g_cur[d], 1);
    g_es[pos] = s;
    g_ew[pos] = g_dinv[s] * g_dinv[d];
}

// ---------------------------------------------------------------- plain GEMM  g_xh = A @ W
// mode 0: A = x (ext); mode 1: A = g_h. Tile 64x128, 256 threads.
// Thread owns rows ty+16i (i<4), col pairs 2tx+32j (j<4). Same structure that
// profiled at 55us/124regs when fused; standalone it fits 3 CTAs/SM.
__global__ __launch_bounds__(256, 3)
void k_gemm(const float* __restrict__ Aext, const float* __restrict__ Wext, int mode) {
    __shared__ __align__(16) float As[64][33];
    __shared__ __align__(16) float Ws[32][128];
    const float* A = (mode == 0) ? Aext : g_h;
    const float* W = Wext;

    int tx = threadIdx.x & 15;
    int ty = threadIdx.x >> 4;
    int tid = threadIdx.x;
    int row0 = blockIdx.x * 64;

    ull acc[4][4];
#pragma unroll
    for (int i = 0; i < 4; i++)
#pragma unroll
        for (int j = 0; j < 4; j++) acc[i][j] = 0ull;

    for (int kc = 0; kc < CH; kc += 32) {
#pragma unroll
        for (int i = tid; i < 64 * 32; i += 256) {
            int r = i >> 5, kk = i & 31;
            int gr = row0 + r;
            As[r][kk] = (gr < NN) ? A[(size_t)gr * CH + kc + kk] : 0.0f;
        }
#pragma unroll
        for (int i = tid; i < 32 * 128; i += 256) {
            int r = i >> 7, c = i & 127;
            Ws[r][c] = W[(kc + r) * CH + c];
        }
        __syncthreads();
#pragma unroll
        for (int kk = 0; kk < 32; kk++) {
            ull aa[4], w2[4];
#pragma unroll
            for (int i = 0; i < 4; i++) aa[i] = dup2(As[ty + 16 * i][kk]);
#pragma unroll
            for (int j = 0; j < 4; j++)
                w2[j] = *(const ull*)&Ws[kk][2 * tx + 32 * j];
#pragma unroll
            for (int i = 0; i < 4; i++)
#pragma unroll
                for (int j = 0; j < 4; j++) ffma2(acc[i][j], aa[i], w2[j]);
        }
        __syncthreads();
    }

#pragma unroll
    for (int i = 0; i < 4; i++) {
        int gr = row0 + ty + 16 * i;
        if (gr < NN) {
#pragma unroll
            for (int j = 0; j < 4; j++) {
                int c = 2 * tx + 32 * j;
                *(ull*)&g_xh[(size_t)gr * CH + c] = acc[i][j];
            }
        }
    }
}

// ---------------------------------------------------------------- head GEMM  (g_h @ g_Wh + g_bh) -> mu/lv/z/mask
// Same tiling; separate kernel so the fat epilogue doesn't tax the plain GEMMs.
__global__ __launch_bounds__(256, 2)
void k_gemm_head(const int* __restrict__ batch, const float* __restrict__ eps,
                 float* __restrict__ out) {
    __shared__ __align__(16) float As[64][33];
    __shared__ __align__(16) float Ws[32][128];
    const float* A = g_h;
    const float* W = g_Wh;

    int tx = threadIdx.x & 15;
    int ty = threadIdx.x >> 4;
    int tid = threadIdx.x;
    int row0 = blockIdx.x * 64;

    ull acc[4][4];
#pragma unroll
    for (int i = 0; i < 4; i++)
#pragma unroll
        for (int j = 0; j < 4; j++) acc[i][j] = 0ull;

    for (int kc = 0; kc < CH; kc += 32) {
#pragma unroll
        for (int i = tid; i < 64 * 32; i += 256) {
            int r = i >> 5, kk = i & 31;
            int gr = row0 + r;
            As[r][kk] = (gr < NN) ? A[(size_t)gr * CH + kc + kk] : 0.0f;
        }
#pragma unroll
        for (int i = tid; i < 32 * 128; i += 256) {
            int r = i >> 7, c = i & 127;
            Ws[r][c] = W[(kc + r) * CH + c];
        }
        __syncthreads();
#pragma unroll
        for (int kk = 0; kk < 32; kk++) {
            ull aa[4], w2[4];
#pragma unroll
            for (int i = 0; i < 4; i++) aa[i] = dup2(As[ty + 16 * i][kk]);
#pragma unroll
            for (int j = 0; j < 4; j++)
                w2[j] = *(const ull*)&Ws[kk][2 * tx + 32 * j];
#pragma unroll
            for (int i = 0; i < 4; i++)
#pragma unroll
                for (int j = 0; j < 4; j++) ffma2(acc[i][j], aa[i], w2[j]);
        }
        __syncthreads();
    }

    // cols 0..63 = mu, 64..127 = lv; j and j+2 share latent index
#pragma unroll
    for (int i = 0; i < 4; i++) {
        int gr = row0 + ty + 16 * i;
        if (gr >= NN) continue;
        int b = batch[gr];
        int pos = gr - g_ptr[b];
#pragma unroll
        for (int jp = 0; jp < 2; jp++) {
            int c = 2 * tx + 32 * jp;                  // latent index (even)
            ull mu2 = acc[i][jp];
            ull lv2 = acc[i][jp + 2];
            fadd2(mu2, mu2, *(const ull*)&g_bh[c]);
            fadd2(lv2, lv2, *(const ull*)&g_bh[c + 64]);
            *(ull*)&out[MU_OFF + (size_t)gr * LATD + c] = mu2;
            *(ull*)&out[LV_OFF + (size_t)gr * LATD + c] = lv2;
            float2 m = *(float2*)&mu2;
            float2 l = *(float2*)&lv2;
            ull e2 = *(const ull*)&eps[(size_t)gr * LATD + c];
            float2 ef = *(float2*)&e2;
            float2 zz;
            zz.x = fmaf(ef.x, fast_exp(0.5f * fminf(fmaxf(l.x, -20.0f), 20.0f)), m.x);
            zz.y = fmaf(ef.y, fast_exp(0.5f * fminf(fmaxf(l.y, -20.0f), 20.0f)), m.y);
            if (pos < MAXN) {
                *(ull*)&g_z[((size_t)b * MAXN + pos) * LATD + c] = *(ull*)&zz;
                if (c == 0) out[MASK_OFF + b * MAXN + pos] = 1.0f;
            }
        }
    }
}

// ---------------------------------------------------------------- CSR aggregation: warp per node
// 8-edge unroll: 8 float4 gathers in flight to hide L2 latency (234-262 cyc).
__global__ __launch_bounds__(256)
void k_agg(const float* __restrict__ bias) {
    int node = (blockIdx.x * blockDim.x + threadIdx.x) >> 5;
    if (node >= NN) return;
    int lane = threadIdx.x & 31;

    float dv = g_dinv[node];
    ull sn = dup2(dv * dv);
    float4 self = ((const float4*)(g_xh + (size_t)node * CH))[lane];
    ull acc0 = 0ull, acc1 = 0ull;
    ffma2(acc0, sn, *(ull*)&self.x);
    ffma2(acc1, sn, *(ull*)&self.z);

    int e = g_off[node];
    int end = g_off[node + 1];

    for (; e + 8 <= end; e += 8) {
        float4 v[8];
        ull w[8];
#pragma unroll
        for (int q = 0; q < 8; q++) {
            v[q] = ((const float4*)(g_xh + (size_t)g_es[e + q] * CH))[lane];
            w[q] = dup2(g_ew[e + q]);
        }
#pragma unroll
        for (int q = 0; q < 8; q++) {
            ffma2(acc0, w[q], *(ull*)&v[q].x);
            ffma2(acc1, w[q], *(ull*)&v[q].z);
        }
    }
    for (; e + 2 <= end; e += 2) {
        int s0 = g_es[e], s1 = g_es[e + 1];
        ull w0 = dup2(g_ew[e]), w1 = dup2(g_ew[e + 1]);
        float4 v0 = ((const float4*)(g_xh + (size_t)s0 * CH))[lane];
        float4 v1 = ((const float4*)(g_xh + (size_t)s1 * CH))[lane];
        ffma2(acc0, w0, *(ull*)&v0.x); ffma2(acc1, w0, *(ull*)&v0.z);
        ffma2(acc0, w1, *(ull*)&v1.x); ffma2(acc1, w1, *(ull*)&v1.z);
    }
    if (e < end) {
        int s = g_es[e];
        ull w = dup2(g_ew[e]);
        float4 v = ((const float4*)(g_xh + (size_t)s * CH))[lane];
        ffma2(acc0, w, *(ull*)&v.x);
        ffma2(acc1, w, *(ull*)&v.z);
    }

    float4 b = ((const float4*)bias)[lane];
    float2 a0 = *(float2*)&acc0;
    float2 a1 = *(float2*)&acc1;
    float4 r;
    r.x = fmaxf(a0.x + b.x, 0.0f);
    r.y = fmaxf(a0.y + b.y, 0.0f);
    r.z = fmaxf(a1.x + b.z, 0.0f);
    r.w = fmaxf(a1.y + b.w, 0.0f);
    ((float4*)(g_h + (size_t)node * CH))[lane] = r;
}

// ---------------------------------------------------------------- decoder: per-graph z @ z^T -> sigmoid
// tile 160x160, 512 threads; thread owns rows ty+32i (i<5), col pairs 2tx+32j (j<5)
__global__ __launch_bounds__(512, 1)
void k_adj(const float* __restrict__ dec_bias, float* __restrict__ out) {
    __shared__ __align__(16) float As [160][65];
    __shared__ __align__(16) float BsT[64][162];
    int b = blockIdx.z;
    int r0 = blockIdx.y * 160;
    int c0 = blockIdx.x * 160;
    int tx = threadIdx.x & 15;
    int ty = threadIdx.x >> 4;          // 0..31
    int tid = threadIdx.x;
    const float* zb = g_z + (size_t)b * MAXN * LATD;

#pragma unroll
    for (int i = tid; i < 160 * 16; i += 512) {
        int r = i >> 4, k4 = (i & 15) * 4;
        float4 va = *(const float4*)&zb[(size_t)(r0 + r) * LATD + k4];
        As[r][k4] = va.x; As[r][k4+1] = va.y; As[r][k4+2] = va.z; As[r][k4+3] = va.w;
        float4 vb = *(const float4*)&zb[(size_t)(c0 + r) * LATD + k4];
        BsT[k4  ][r] = vb.x;
        BsT[k4+1][r] = vb.y;
        BsT[k4+2][r] = vb.z;
        BsT[k4+3][r] = vb.w;
    }
    __syncthreads();

    ull acc[5][5];
#pragma unroll
    for (int i = 0; i < 5; i++)
#pragma unroll
        for (int j = 0; j < 5; j++) acc[i][j] = 0ull;

#pragma unroll 4
    for (int k = 0; k < 64; k++) {
        ull aa[5], c2[5];
#pragma unroll
        for (int i = 0; i < 5; i++) aa[i] = dup2(As[ty + 32 * i][k]);
#pragma unroll
        for (int j = 0; j < 5; j++)
            c2[j] = *(const ull*)&BsT[k][2 * tx + 32 * j];
#pragma unroll
        for (int i = 0; i < 5; i++)
#pragma unroll
            for (int j = 0; j < 5; j++) ffma2(acc[i][j], aa[i], c2[j]);
    }

    float bias = dec_bias[0];
    const float SC = 0.125f;
#pragma unroll
    for (int i = 0; i < 5; i++) {
        int row = r0 + ty + 32 * i;
        size_t base = ((size_t)b * MAXN + row) * MAXN + c0;
#pragma unroll
        for (int j = 0; j < 5; j++) {
            int cp = 2 * tx + 32 * j;
            float2 a = *(float2*)&acc[i][j];
            float2 o;
            o.x = fast_sigmoid(fmaf(SC, a.x, bias));
            o.y = fast_sigmoid(fmaf(SC, a.y, bias));
            *(float2*)&out[base + cp] = o;
        }
    }
}

// ================================================================ launch
extern "C" void kernel_launch(void* const* d_in, const int* in_sizes, int n_in,
                              void* d_out, int out_size) {
    const float* x    = (const float*)d_in[0];
    const int*   ei   = (const int*)  d_in[1];
    const int*   batch= (const int*)  d_in[2];
    const float* eps  = (const float*)d_in[3];
    const float* W1   = (const float*)d_in[4];
    const float* b1   = (const float*)d_in[5];
    const float* W2   = (const float*)d_in[6];
    const float* b2   = (const float*)d_in[7];
    const float* Wmu  = (const float*)d_in[8];
    const float* bmu  = (const float*)d_in[9];
    const float* Wlv  = (const float*)d_in[10];
    const float* blv  = (const float*)d_in[11];
    const float* dbias= (const float*)d_in[12];
    float* out = (float*)d_out;

    const int* src = ei;
    const int* dst = ei + EE;

    int gemm_blocks = (NN + 63) / 64;
    int agg_blocks  = (NN * 32 + 255) / 256;

    // our 4th launch is what ncu captures: keep the plain mode-0 GEMM there.
    k_zero<<<(NG*MAXN*LATD + 255) / 256, 256>>>(out, Wmu, bmu, Wlv, blv);   // 1
    k_hist<<<(EE + 255) / 256, 256>>>(dst);                                  // 2
    k_rsqrt<<<(NN + 255) / 256, 256>>>(batch);                               // 3
    k_gemm<<<gemm_blocks, 256>>>(x, W1, 0);                                  // 4 <- profiled
    k_scan1<<<NBLK, 256>>>();                                                // 5
    k_scan2<<<1, 256>>>();                                                   // 6
    k_scan3<<<NBLK, 256>>>();                                                // 7
    k_scatter<<<(EE + 255) / 256, 256>>>(src, dst);                          // 8
    k_agg<<<agg_blocks, 256>>>(b1);                                          // 9
    k_gemm<<<gemm_blocks, 256>>>(nullptr, W2, 1);                            // 10
    k_agg<<<agg_blocks, 256>>>(b2);                                          // 11
    k_gemm_head<<<gemm_blocks, 256>>>(batch, eps, out);                      // 12
    dim3 agrid(2, 2, NG);
    k_adj<<<agrid, 512>>>(dbias, out);                                       // 13
}

// round 17
// speedup vs baseline: 1.5373x; 1.0458x over previous
#include <cuda_runtime.h>
#include <math.h>

#define NN 50000
#define EE 800000
#define CH 128
#define LATD 64
#define NG 256
#define MAXN 320

// output layout (floats): adj | mu | logvar | mask
#define ADJ_OFF 0
#define MU_OFF   (NG*MAXN*MAXN)
#define LV_OFF   (MU_OFF + NN*LATD)
#define MASK_OFF (LV_OFF + NN*LATD)

#define NBLK 196                        // ceil(NN/256)

// ---- scratch (device globals; never passed as kernel args from host) ----
__device__ float g_dinv[NN];
__device__ float g_xh [NN*CH];
__device__ float g_h  [NN*CH];
__device__ float g_z  [NG*MAXN*LATD];
__device__ float g_Wh [CH*CH];
__device__ __align__(16) float g_bh [CH];
__device__ int   g_cnt[NG];
__device__ int   g_ptr[NG];
__device__ int   g_ideg[NN];
__device__ int   g_off [NN + 1];
__device__ int   g_cur [NN];
__device__ int   g_bsum[NBLK];
__device__ int   g_boff[NBLK];
__device__ int   g_es  [EE];
__device__ float g_ew  [EE];

typedef unsigned long long ull;

__device__ __forceinline__ ull dup2(float a) {
    ull r; asm("mov.b64 %0, {%1, %1};" : "=l"(r) : "f"(a)); return r;
}
__device__ __forceinline__ void ffma2(ull& d, ull a, ull b) {
    asm("fma.rn.f32x2 %0, %1, %2, %3;" : "=l"(d) : "l"(a), "l"(b), "l"(d));
}
__device__ __forceinline__ void fadd2(ull& d, ull a, ull b) {
    asm("add.rn.f32x2 %0, %1, %2;" : "=l"(d) : "l"(a), "l"(b));
}

// FMA-only e^t (t bounded |t| <= ~30): 2^(t*log2e) via floor + deg-5 poly
__device__ __forceinline__ float fast_exp(float t) {
    float u = fminf(fmaxf(t * 1.4426950408889634f, -30.0f), 30.0f);
    float fl = floorf(u);
    float fr = u - fl;
    float p = 1.33336498e-3f;
    p = fmaf(p, fr, 9.61011722e-3f);
    p = fmaf(p, fr, 5.55036540e-2f);
    p = fmaf(p, fr, 2.40226506e-1f);
    p = fmaf(p, fr, 6.93147182e-1f);
    p = fmaf(p, fr, 1.0f);
    float s = __int_as_float(((int)fl + 127) << 23);
    return p * s;
}

__device__ __forceinline__ float fast_sigmoid(float t) {
    float ex = fast_exp(t);
    float d = 1.0f + ex;
    float r = __int_as_float(0x7EF127EA - __float_as_int(d));
    r = r * (2.0f - d * r);
    r = r * (2.0f - d * r);
    return ex * r;                       // sigmoid(t) = e^t / (1+e^t)
}

// ---------------------------------------------------------------- zero / init (+ head packing fused)
__global__ void k_zero(float* __restrict__ out,
                       const float* __restrict__ Wmu, const float* __restrict__ bmu,
                       const float* __restrict__ Wlv, const float* __restrict__ blv) {
    int i = blockIdx.x * blockDim.x + threadIdx.x;
    if (i < NG*MAXN*LATD) g_z[i] = 0.0f;
    if (i < NN)           g_ideg[i] = 0;
    if (i < NG)           g_cnt[i] = 0;
    if (i < NG*MAXN)      out[MASK_OFF + i] = 0.0f;
    if (i < CH * CH) {
        int k = i >> 7, j = i & 127;
        g_Wh[i] = (j < LATD) ? Wmu[k * LATD + j] : Wlv[k * LATD + (j - LATD)];
    }
    if (i < CH) g_bh[i] = (i < LATD) ? bmu[i] : blv[i - LATD];
}

__global__ void k_hist(const int* __restrict__ dst) {
    int e = blockIdx.x * blockDim.x + threadIdx.x;
    if (e < EE) atomicAdd(&g_ideg[dst[e]], 1);
}

// ---- scan phase 1, fused with dinv/graph-count (both read g_ideg / per-node) ----
__global__ void k_scan1(const int* __restrict__ batch) {
    int idx = blockIdx.x * 256 + threadIdx.x;
    int v = (idx < NN) ? g_ideg[idx] : 0;
    if (idx < NN) {
        g_dinv[idx] = rsqrtf((float)(v + 1));   // +1 self-loop
        atomicAdd(&g_cnt[batch[idx]], 1);
    }
    int lane = threadIdx.x & 31, wid = threadIdx.x >> 5;
    int s = v;
#pragma unroll
    for (int o = 1; o < 32; o <<= 1) {
        int t = __shfl_up_sync(~0u, s, o);
        if (lane >= o) s += t;
    }
    __shared__ int ws[8];
    if (lane == 31) ws[wid] = s;
    __syncthreads();
    if (threadIdx.x < 8) {
        int t = ws[threadIdx.x], u = t;
#pragma unroll
        for (int o = 1; o < 8; o <<= 1) {
            int p = __shfl_up_sync(0xff, u, o);
            if (threadIdx.x >= o) u += p;
        }
        ws[threadIdx.x] = u - t;
    }
    __syncthreads();
    int exc = s - v + ws[wid];
    if (idx < NN) g_off[idx] = exc;
    if (threadIdx.x == 255) g_bsum[blockIdx.x] = exc + v;
}

// scan of block sums + (fused) graph-pointer scan
__global__ void k_scan2() {
    int t = threadIdx.x;
    {
        int v = (t < NBLK) ? g_bsum[t] : 0;
        int lane = t & 31, wid = t >> 5;
        int s = v;
#pragma unroll
        for (int o = 1; o < 32; o <<= 1) {
            int p = __shfl_up_sync(~0u, s, o);
            if (lane >= o) s += p;
        }
        __shared__ int ws[8];
        if (lane == 31) ws[wid] = s;
        __syncthreads();
        if (t < 8) {
            int a = ws[t], u = a;
#pragma unroll
            for (int o = 1; o < 8; o <<= 1) {
                int p = __shfl_up_sync(0xff, u, o);
                if (t >= o) u += p;
            }
            ws[t] = u - a;
        }
        __syncthreads();
        if (t < NBLK) g_boff[t] = s - v + ws[wid];
    }
    __syncthreads();
    // graph ptr scan (NG = 256)
    {
        __shared__ int sp[NG];
        int my = g_cnt[t];
        sp[t] = my;
        __syncthreads();
        for (int off = 1; off < NG; off <<= 1) {
            int v = (t >= off) ? sp[t - off] : 0;
            __syncthreads();
            sp[t] += v;
            __syncthreads();
        }
        g_ptr[t] = sp[t] - my;
    }
}

__global__ void k_scan3() {
    int idx = blockIdx.x * 256 + threadIdx.x;
    if (idx < NN) {
        int o = g_off[idx] + g_boff[blockIdx.x];
        g_off[idx] = o;
        g_cur[idx] = o;
    }
    if (idx == 0) g_off[NN] = EE;
}

__global__ void k_scatter(const int* __restrict__ src, const int* __restrict__ dst) {
    int e = blockIdx.x * blockDim.x + threadIdx.x;
    if (e >= EE) return;
    int s = src[e], d = dst[e];
    int pos = atomicAdd(&g_cur[d], 1);
    g_es[pos] = s;
    g_ew[pos] = g_dinv[s] * g_dinv[d];
}

// ---------------------------------------------------------------- GEMM loads: k-paired smem fill
// Ws2[kp][4p..4p+3] = { W[2kp][2p], W[2kp][2p+1], W[2kp+1][2p], W[2kp+1][2p+1] }
__device__ __forceinline__ void gemm_fill(float (*As)[34], float (*Ws2)[256],
                                          const float* A, const float* W,
                                          int row0, int kc, int tid) {
#pragma unroll
    for (int i = tid; i < 64 * 32; i += 256) {
        int r = i >> 5, kk = i & 31;
        int gr = row0 + r;
        As[r][kk] = (gr < NN) ? A[(size_t)gr * CH + kc + kk] : 0.0f;
    }
#pragma unroll
    for (int i = tid; i < 16 * 64; i += 256) {
        int kp = i >> 6, p = i & 63;
        float2 w0 = *(const float2*)&W[(size_t)(kc + 2 * kp)     * CH + 2 * p];
        float2 w1 = *(const float2*)&W[(size_t)(kc + 2 * kp + 1) * CH + 2 * p];
        *(float4*)&Ws2[kp][4 * p] = make_float4(w0.x, w0.y, w1.x, w1.y);
    }
}

// inner product over one 32-k chunk (16 k-pairs)
__device__ __forceinline__ void gemm_mac(float (*As)[34], float (*Ws2)[256],
                                         ull (*acc)[4], int tx, int ty) {
#pragma unroll
    for (int kp = 0; kp < 16; kp++) {
        ull a2[4];
        float4 w[4];
#pragma unroll
        for (int i = 0; i < 4; i++) a2[i] = *(const ull*)&As[ty + 16 * i][2 * kp];
#pragma unroll
        for (int j = 0; j < 4; j++) w[j] = *(const float4*)&Ws2[kp][4 * (tx + 16 * j)];
#pragma unroll
        for (int i = 0; i < 4; i++) {
            float2 af = *(float2*)&a2[i];
            ull a0 = dup2(af.x), a1 = dup2(af.y);
#pragma unroll
            for (int j = 0; j < 4; j++) {
                ffma2(acc[i][j], a0, *(ull*)&w[j].x);
                ffma2(acc[i][j], a1, *(ull*)&w[j].z);
            }
        }
    }
}

// ---------------------------------------------------------------- plain GEMM  g_xh = A @ W
// mode 0: A = x (ext); mode 1: A = g_h. Tile 64x128, 256 threads.
__global__ __launch_bounds__(256, 3)
void k_gemm(const float* __restrict__ Aext, const float* __restrict__ Wext, int mode) {
    __shared__ __align__(16) float As[64][34];
    __shared__ __align__(16) float Ws2[16][256];
    const float* A = (mode == 0) ? Aext : g_h;

    int tx = threadIdx.x & 15;
    int ty = threadIdx.x >> 4;
    int tid = threadIdx.x;
    int row0 = blockIdx.x * 64;

    ull acc[4][4];
#pragma unroll
    for (int i = 0; i < 4; i++)
#pragma unroll
        for (int j = 0; j < 4; j++) acc[i][j] = 0ull;

    for (int kc = 0; kc < CH; kc += 32) {
        gemm_fill(As, Ws2, A, Wext, row0, kc, tid);
        __syncthreads();
        gemm_mac(As, Ws2, acc, tx, ty);
        __syncthreads();
    }

#pragma unroll
    for (int i = 0; i < 4; i++) {
        int gr = row0 + ty + 16 * i;
        if (gr < NN) {
#pragma unroll
            for (int j = 0; j < 4; j++) {
                int c = 2 * tx + 32 * j;
                *(ull*)&g_xh[(size_t)gr * CH + c] = acc[i][j];
            }
        }
    }
}

// ---------------------------------------------------------------- head GEMM  (g_h @ g_Wh + g_bh) -> mu/lv/z/mask
__global__ __launch_bounds__(256, 2)
void k_gemm_head(const int* __restrict__ batch, const float* __restrict__ eps,
                 float* __restrict__ out) {
    __shared__ __align__(16) float As[64][34];
    __shared__ __align__(16) float Ws2[16][256];

    int tx = threadIdx.x & 15;
    int ty = threadIdx.x >> 4;
    int tid = threadIdx.x;
    int row0 = blockIdx.x * 64;

    ull acc[4][4];
#pragma unroll
    for (int i = 0; i < 4; i++)
#pragma unroll
        for (int j = 0; j < 4; j++) acc[i][j] = 0ull;

    for (int kc = 0; kc < CH; kc += 32) {
        gemm_fill(As, Ws2, g_h, g_Wh, row0, kc, tid);
        __syncthreads();
        gemm_mac(As, Ws2, acc, tx, ty);
        __syncthreads();
    }

    // cols 0..63 = mu, 64..127 = lv; j and j+2 share latent index
#pragma unroll
    for (int i = 0; i < 4; i++) {
        int gr = row0 + ty + 16 * i;
        if (gr >= NN) continue;
        int b = batch[gr];
        int pos = gr - g_ptr[b];
#pragma unroll
        for (int jp = 0; jp < 2; jp++) {
            int c = 2 * tx + 32 * jp;                  // latent index (even)
            ull mu2 = acc[i][jp];
            ull lv2 = acc[i][jp + 2];
            fadd2(mu2, mu2, *(const ull*)&g_bh[c]);
            fadd2(lv2, lv2, *(const ull*)&g_bh[c + 64]);
            *(ull*)&out[MU_OFF + (size_t)gr * LATD + c] = mu2;
            *(ull*)&out[LV_OFF + (size_t)gr * LATD + c] = lv2;
            float2 m = *(float2*)&mu2;
            float2 l = *(float2*)&lv2;
            ull e2 = *(const ull*)&eps[(size_t)gr * LATD + c];
            float2 ef = *(float2*)&e2;
            float2 zz;
            zz.x = fmaf(ef.x, fast_exp(0.5f * fminf(fmaxf(l.x, -20.0f), 20.0f)), m.x);
            zz.y = fmaf(ef.y, fast_exp(0.5f * fminf(fmaxf(l.y, -20.0f), 20.0f)), m.y);
            if (pos < MAXN) {
                *(ull*)&g_z[((size_t)b * MAXN + pos) * LATD + c] = *(ull*)&zz;
                if (c == 0) out[MASK_OFF + b * MAXN + pos] = 1.0f;
            }
        }
    }
}

// ---------------------------------------------------------------- CSR aggregation: warp per node
// 8-edge unroll: 8 float4 gathers in flight (L2 latency 234-262 cyc; LTS-cap bound).
__global__ __launch_bounds__(256)
void k_agg(const float* __restrict__ bias) {
    int node = (blockIdx.x * blockDim.x + threadIdx.x) >> 5;
    if (node >= NN) return;
    int lane = threadIdx.x & 31;

    float dv = g_dinv[node];
    ull sn = dup2(dv * dv);
    float4 self = ((const float4*)(g_xh + (size_t)node * CH))[lane];
    ull acc0 = 0ull, acc1 = 0ull;
    ffma2(acc0, sn, *(ull*)&self.x);
    ffma2(acc1, sn, *(ull*)&self.z);

    int e = g_off[node];
    int end = g_off[node + 1];

    for (; e + 8 <= end; e += 8) {
        float4 v[8];
        ull w[8];
#pragma unroll
        for (int q = 0; q < 8; q++) {
            v[q] = ((const float4*)(g_xh + (size_t)g_es[e + q] * CH))[lane];
            w[q] = dup2(g_ew[e + q]);
        }
#pragma unroll
        for (int q = 0; q < 8; q++) {
            ffma2(acc0, w[q], *(ull*)&v[q].x);
            ffma2(acc1, w[q], *(ull*)&v[q].z);
        }
    }
    for (; e + 2 <= end; e += 2) {
        int s0 = g_es[e], s1 = g_es[e + 1];
        ull w0 = dup2(g_ew[e]), w1 = dup2(g_ew[e + 1]);
        float4 v0 = ((const float4*)(g_xh + (size_t)s0 * CH))[lane];
        float4 v1 = ((const float4*)(g_xh + (size_t)s1 * CH))[lane];
        ffma2(acc0, w0, *(ull*)&v0.x); ffma2(acc1, w0, *(ull*)&v0.z);
        ffma2(acc0, w1, *(ull*)&v1.x); ffma2(acc1, w1, *(ull*)&v1.z);
    }
    if (e < end) {
        int s = g_es[e];
        ull w = dup2(g_ew[e]);
        float4 v = ((const float4*)(g_xh + (size_t)s * CH))[lane];
        ffma2(acc0, w, *(ull*)&v.x);
        ffma2(acc1, w, *(ull*)&v.z);
    }

    float4 b = ((const float4*)bias)[lane];
    float2 a0 = *(float2*)&acc0;
    float2 a1 = *(float2*)&acc1;
    float4 r;
    r.x = fmaxf(a0.x + b.x, 0.0f);
    r.y = fmaxf(a0.y + b.y, 0.0f);
    r.z = fmaxf(a1.x + b.z, 0.0f);
    r.w = fmaxf(a1.y + b.w, 0.0f);
    ((float4*)(g_h + (size_t)node * CH))[lane] = r;
}

// ---------------------------------------------------------------- decoder: per-graph z @ z^T -> sigmoid
// tile 160x160, 512 threads; thread owns rows ty+32i (i<5), col pairs 2tx+32j (j<5)
__global__ __launch_bounds__(512, 1)
void k_adj(const float* __restrict__ dec_bias, float* __restrict__ out) {
    __shared__ __align__(16) float As [160][65];
    __shared__ __align__(16) float BsT[64][162];
    int b = blockIdx.z;
    int r0 = blockIdx.y * 160;
    int c0 = blockIdx.x * 160;
    int tx = threadIdx.x & 15;
    int ty = threadIdx.x >> 4;          // 0..31
    int tid = threadIdx.x;
    const float* zb = g_z + (size_t)b * MAXN * LATD;

#pragma unroll
    for (int i = tid; i < 160 * 16; i += 512) {
        int r = i >> 4, k4 = (i & 15) * 4;
        float4 va = *(const float4*)&zb[(size_t)(r0 + r) * LATD + k4];
        As[r][k4] = va.x; As[r][k4+1] = va.y; As[r][k4+2] = va.z; As[r][k4+3] = va.w;
        float4 vb = *(const float4*)&zb[(size_t)(c0 + r) * LATD + k4];
        BsT[k4  ][r] = vb.x;
        BsT[k4+1][r] = vb.y;
        BsT[k4+2][r] = vb.z;
        BsT[k4+3][r] = vb.w;
    }
    __syncthreads();

    ull acc[5][5];
#pragma unroll
    for (int i = 0; i < 5; i++)
#pragma unroll
        for (int j = 0; j < 5; j++) acc[i][j] = 0ull;

#pragma unroll 4
    for (int k = 0; k < 64; k++) {
        ull aa[5], c2[5];
#pragma unroll
        for (int i = 0; i < 5; i++) aa[i] = dup2(As[ty + 32 * i][k]);
#pragma unroll
        for (int j = 0; j < 5; j++)
            c2[j] = *(const ull*)&BsT[k][2 * tx + 32 * j];
#pragma unroll
        for (int i = 0; i < 5; i++)
#pragma unroll
            for (int j = 0; j < 5; j++) ffma2(acc[i][j], aa[i], c2[j]);
    }

    float bias = dec_bias[0];
    const float SC = 0.125f;
#pragma unroll
    for (int i = 0; i < 5; i++) {
        int row = r0 + ty + 32 * i;
        size_t base = ((size_t)b * MAXN + row) * MAXN + c0;
#pragma unroll
        for (int j = 0; j < 5; j++) {
            int cp = 2 * tx + 32 * j;
            float2 a = *(float2*)&acc[i][j];
            float2 o;
            o.x = fast_sigmoid(fmaf(SC, a.x, bias));
            o.y = fast_sigmoid(fmaf(SC, a.y, bias));
            *(float2*)&out[base + cp] = o;
        }
    }
}

// ================================================================ launch
extern "C" void kernel_launch(void* const* d_in, const int* in_sizes, int n_in,
                              void* d_out, int out_size) {
    const float* x    = (const float*)d_in[0];
    const int*   ei   = (const int*)  d_in[1];
    const int*   batch= (const int*)  d_in[2];
    const float* eps  = (const float*)d_in[3];
    const float* W1   = (const float*)d_in[4];
    const float* b1   = (const float*)d_in[5];
    const float* W2   = (const float*)d_in[6];
    const float* b2   = (const float*)d_in[7];
    const float* Wmu  = (const float*)d_in[8];
    const float* bmu  = (const float*)d_in[9];
    const float* Wlv  = (const float*)d_in[10];
    const float* blv  = (const float*)d_in[11];
    const float* dbias= (const float*)d_in[12];
    float* out = (float*)d_out;

    const int* src = ei;
    const int* dst = ei + EE;

    int gemm_blocks = (NN + 63) / 64;
    int agg_blocks  = (NN * 32 + 255) / 256;

    // our 4th launch is what ncu captures: keep the plain mode-0 GEMM there.
    k_zero<<<(NG*MAXN*LATD + 255) / 256, 256>>>(out, Wmu, bmu, Wlv, blv);   // 1
    k_hist<<<(EE + 255) / 256, 256>>>(dst);                                  // 2
    k_scan1<<<NBLK, 256>>>(batch);                                           // 3 (scan + dinv + cnt)
    k_gemm<<<gemm_blocks, 256>>>(x, W1, 0);                                  // 4 <- profiled
    k_scan2<<<1, 256>>>();                                                   // 5
    k_scan3<<<NBLK, 256>>>();                                                // 6
    k_scatter<<<(EE + 255) / 256, 256>>>(src, dst);                          // 7
    k_agg<<<agg_blocks, 256>>>(b1);                                          // 8
    k_gemm<<<gemm_blocks, 256>>>(nullptr, W2, 1);                            // 9
    k_agg<<<agg_blocks, 256>>>(b2);                                          // 10
    k_gemm_head<<<gemm_blocks, 256>>>(batch, eps, out);                      // 11
    dim3 agrid(2, 2, NG);
    k_adj<<<agrid, 512>>>(dbias, out);                                       // 12
}